// round 2
// baseline (speedup 1.0000x reference)
#include <cuda_runtime.h>
#include <cstdint>

#define BB 8
#define CC 8
#define HH 512
#define WW 512
#define PLANE (HH*WW)                 // 262144
#define PIX   (BB*HH*WW)              // 2097152
#define NEL   (BB*CC*HH*WW)           // 16777216

#define TW 32
#define TH 16
#define NTHREADS 256
#define NBLKX (WW/TW)                 // 16
#define NBLKY (HH/TH)                 // 32
#define NBLK  (NBLKX*NBLKY*BB)        // 4096

#define HROWS (TH+2)                  // 18
#define HCOLS (TW+2)                  // 34
#define PLSZ  (HROWS*HCOLS)           // 612

__device__ double       g_acc;        // static-init 0; reset by last block each run
__device__ unsigned int g_count;      // wraps back to 0 via atomicInc

__device__ __forceinline__ float sigf(float x) {
    return __fdividef(1.0f, 1.0f + __expf(-x));
}
__device__ __forceinline__ float clog(float x) {
    // matches jnp.clip(log(x), -100); log(0) = -inf -> -100
    return fmaxf(__logf(x), -100.0f);
}
// log(a) + log(b) fused into one LG2 when safe (interior); exact fallback
// at borders where a can be exactly 0 (padded shifts) and the clamp is live.
__device__ __forceinline__ float plog2(float a, float b) {
    float p = a * b;
    if (p >= 1e-30f) return __logf(p);
    return clog(a) + clog(b);
}

__global__ void __launch_bounds__(NTHREADS)
bicon_loss_kernel(const float* __restrict__ atts,
                  const float* __restrict__ dets,
                  const float* __restrict__ target,
                  const float* __restrict__ con,
                  float* __restrict__ out)
{
    __shared__ float S[2][HROWS][HCOLS];   // 2 channel planes of sigmoid, 1-halo
    __shared__ float wsum[NTHREADS / 32];

    const int tx  = threadIdx.x & 31;
    const int tyq = threadIdx.x >> 5;      // 0..7, each thread owns rows tyq and tyq+8
    const int x0  = blockIdx.x * TW;
    const int y0  = blockIdx.y * TH;
    const int b   = blockIdx.z;
    const int gx  = x0 + tx;

    const size_t bst = (size_t)CC * PLANE;

    // con_target bitmasks for the 2 pixels (binary targets)
    unsigned msk[2];
    {
        const float* cb = con + (size_t)b * bst + gx;
        unsigned m0 = 0, m1 = 0;
        const int gy0 = y0 + tyq, gy1 = y0 + tyq + 8;
#pragma unroll
        for (int c = 0; c < 8; c++) {
            if (__ldg(cb + c * PLANE + gy0 * WW) > 0.5f) m0 |= (1u << c);
            if (__ldg(cb + c * PLANE + gy1 * WW) > 0.5f) m1 |= (1u << c);
        }
        msk[0] = m0; msk[1] = m1;
    }

    float glo1[2] = {0.f, 0.f}, glo2[2] = {0.f, 0.f};
    float mn2[2]  = {1e30f, 1e30f};
    float bic[2]  = {0.f, 0.f}, conl[2] = {0.f, 0.f};

    // channel-pair offsets: v_k = s_k(p) * s_{7-k}(p + off_k), off_{7-k} = -off_k
    // k=0:(-1,-1) k=1:(-1,0) k=2:(-1,+1) k=3:(0,-1)

    for (int bi = 0; bi < 2; bi++) {
        const float* xb = (bi ? dets : atts) + (size_t)b * bst;
#pragma unroll
        for (int pr = 0; pr < 4; pr++) {
            const int dy = (pr < 3) ? -1 : 0;
            const int dx = (pr == 1) ? 0 : ((pr == 2) ? 1 : -1);

            __syncthreads();   // protect previous iteration's reads
            // cooperative load + sigmoid of channels pr (plane0) and 7-pr (plane1)
            for (int e = threadIdx.x; e < 2 * PLSZ; e += NTHREADS) {
                int pl = (e >= PLSZ);
                int r  = pl ? (e - PLSZ) : e;
                int ly = r / HCOLS, lx = r - ly * HCOLS;
                int gyy = y0 + ly - 1, gxx = x0 + lx - 1;
                int ch  = pl ? (7 - pr) : pr;
                float s = 0.0f;
                if ((unsigned)gyy < (unsigned)HH && (unsigned)gxx < (unsigned)WW)
                    s = sigf(__ldg(xb + ch * PLANE + gyy * WW + gxx));
                (&S[0][0][0])[e] = s;
            }
            __syncthreads();

#pragma unroll
            for (int q = 0; q < 2; q++) {
                const int lr = tyq + q * 8 + 1, lc = tx + 1;
                float sk = S[0][lr][lc];
                float s7 = S[1][lr][lc];
                float vk = sk * S[1][lr + dy][lc + dx];
                float v7 = s7 * S[0][lr - dy][lc - dx];
                if (bi == 0) {
                    glo1[q] += vk + v7;
                } else {
                    glo2[q] += vk + v7;
                    mn2[q]   = fminf(mn2[q], fminf(vk, v7));
                }
                bool tk = (msk[q] >> pr) & 1u;
                bool t7 = (msk[q] >> (7 - pr)) & 1u;
                float Ak = tk ? vk : 1.0f - vk;
                float A7 = t7 ? v7 : 1.0f - v7;
                float Bk = tk ? sk : 1.0f - sk;
                float B7 = t7 ? s7 : 1.0f - s7;
                bic[q]  += plog2(Ak, A7);   // bicon (vote) terms
                conl[q] += plog2(Bk, B7);   // conn  (prob) terms
            }
        }
    }

    // per-pixel final terms
    float contrib = 0.0f;
    {
        const float* tgp = target + (size_t)b * PLANE + gx;
#pragma unroll
        for (int q = 0; q < 2; q++) {
            const int gy = y0 + tyq + q * 8;
            float tg = __ldg(tgp + gy * WW);
            float g1 = glo1[q] * 0.125f;
            float g2 = glo2[q] * 0.125f;
            bool edge = (msk[q] != 0u) && (msk[q] != 255u);
            float de  = edge ? (1.0f - mn2[q]) : g2;
            bool  T   = (tg > 0.5f);
            float b1t = clog(T ? g1 : 1.0f - g1);
            float det = clog(T ? de : 1.0f - de);
            contrib += (0.2f * bic[q] + 0.8f * conl[q]) * (1.0f / (float)NEL)
                     + (b1t + det) * (1.0f / (float)PIX);
        }
    }

    // block reduction
#pragma unroll
    for (int o = 16; o > 0; o >>= 1)
        contrib += __shfl_down_sync(0xFFFFFFFFu, contrib, o);
    if (tx == 0) wsum[tyq] = contrib;
    __syncthreads();

    if (threadIdx.x == 0) {
        float s = 0.0f;
#pragma unroll
        for (int i = 0; i < NTHREADS / 32; i++) s += wsum[i];
        atomicAdd(&g_acc, (double)s);
        __threadfence();
        unsigned old = atomicInc(&g_count, NBLK - 1u);  // wraps to 0 on last
        if (old == NBLK - 1u) {
            // read-and-reset accumulator atomically, write result
            unsigned long long raw =
                atomicExch((unsigned long long*)&g_acc, 0ULL);
            out[0] = -(float)__longlong_as_double(raw);
        }
    }
}

extern "C" void kernel_launch(void* const* d_in, const int* in_sizes, int n_in,
                              void* d_out, int out_size) {
    const float* atts   = (const float*)d_in[0];
    const float* dets   = (const float*)d_in[1];
    const float* target = (const float*)d_in[2];
    const float* con    = (const float*)d_in[3];
    float* out = (float*)d_out;

    dim3 grid(NBLKX, NBLKY, BB);
    bicon_loss_kernel<<<grid, NTHREADS>>>(atts, dets, target, con, out);
}

// round 3
// speedup vs baseline: 1.8616x; 1.8616x over previous
#include <cuda_runtime.h>
#include <cstdint>

#define BB 8
#define CC 8
#define HH 512
#define WW 512
#define PLANE (HH*WW)                 // 262144
#define PIX   (BB*HH*WW)              // 2097152
#define NEL   (BB*CC*HH*WW)           // 16777216
#define NTHREADS 256
#define NBLK (PIX/NTHREADS)           // 8192

__device__ double       g_acc;        // zero-init; reset by last block each run
__device__ unsigned int g_count;      // wraps to 0 via atomicInc

// sigmoid via single-MUFU tanh.approx: sigma(x) = 0.5 + 0.5*tanh(x/2)
__device__ __forceinline__ float sigt(float x) {
    float t;
    asm("tanh.approx.f32 %0, %1;" : "=f"(t) : "f"(0.5f * x));
    return fmaf(0.5f, t, 0.5f);
}

__device__ __forceinline__ float clog(float x) {
    // matches jnp.clip(log(x), -100); log(0) = -inf -> -100
    return fmaxf(__logf(x), -100.0f);
}

// log(a0)+log(a1)+log(a2)+log(a3) in ONE LG2 when the product is safely
// normal; exact clamped fallback otherwise (borders where padded v=0).
__device__ __forceinline__ float flog4(float a0, float a1, float a2, float a3) {
    float p = (a0 * a1) * (a2 * a3);
    if (p >= 1e-30f) return __logf(p);
    return clog(a0) + clog(a1) + clog(a2) + clog(a3);
}
__device__ __forceinline__ float flog2p(float a0, float a1) {
    float p = a0 * a1;
    if (p >= 1e-30f) return __logf(p);
    return clog(a0) + clog(a1);
}

// sigmoid of neighbor element, 0 if out of bounds (zero-padded shift of the
// PROBABILITY map, per reference)
__device__ __forceinline__ float nsig(const float* __restrict__ xb, int c,
                                      int h, int w, int dh, int dw) {
    int hh = h + dh, ww = w + dw;
    if ((unsigned)hh >= (unsigned)HH || (unsigned)ww >= (unsigned)WW) return 0.0f;
    return sigt(__ldg(xb + c * PLANE + hh * WW + ww));
}

struct BranchRes { float bicon, conn, glo, vmin; };

__device__ __forceinline__ BranchRes branch_eval(const float* __restrict__ xb,
                                                 unsigned msk, int h, int w) {
    const float* px = xb + h * WW + w;
    float s[8];
#pragma unroll
    for (int c = 0; c < 8; c++) s[c] = sigt(__ldg(px + c * PLANE));

    float n1 = nsig(xb, 4, h, w,  0, -1);   // right        = c4[h, w-1]
    float n2 = nsig(xb, 3, h, w,  0, +1);   // left         = c3[h, w+1]
    float n3 = nsig(xb, 6, h, w, -1,  0);   // bottom       = c6[h-1, w]
    float n4 = nsig(xb, 1, h, w, +1,  0);   // up           = c1[h+1, w]
    float n5 = nsig(xb, 5, h, w, -1, +1);   // left_bottom  = c5[h-1, w+1]
    float n6 = nsig(xb, 2, h, w, +1, -1);   // right_above  = c2[h+1, w-1]
    float n7 = nsig(xb, 7, h, w, -1, -1);   // right_bottom = c7[h-1, w-1]
    float n8 = nsig(xb, 0, h, w, +1, +1);   // left_above   = c0[h+1, w+1]

    // vote_out channel order: [a7, a3, a5, a1, a2, a6, a4, a8]
    float v[8];
    v[0] = s[0] * n7;  // a7
    v[1] = s[1] * n3;  // a3
    v[2] = s[2] * n5;  // a5
    v[3] = s[3] * n1;  // a1
    v[4] = s[4] * n2;  // a2
    v[5] = s[5] * n6;  // a6
    v[6] = s[6] * n4;  // a4
    v[7] = s[7] * n8;  // a8

    float A[8], Bt[8];
    float glo = 0.0f, mn = 1e30f;
#pragma unroll
    for (int k = 0; k < 8; k++) {
        glo += v[k];
        mn = fminf(mn, v[k]);
        bool t = (msk >> k) & 1u;
        A[k]  = t ? v[k] : 1.0f - v[k];
        Bt[k] = t ? s[k] : 1.0f - s[k];
    }

    BranchRes r;
    r.bicon = flog4(A[0], A[1], A[2], A[3]) + flog4(A[4], A[5], A[6], A[7]);
    r.conn  = flog4(Bt[0], Bt[1], Bt[2], Bt[3]) + flog4(Bt[4], Bt[5], Bt[6], Bt[7]);
    r.glo   = glo * 0.125f;
    r.vmin  = mn;
    return r;
}

__global__ void __launch_bounds__(NTHREADS)
bicon_loss_kernel(const float* __restrict__ atts,
                  const float* __restrict__ dets,
                  const float* __restrict__ target,
                  const float* __restrict__ con,
                  float* __restrict__ out)
{
    int idx = blockIdx.x * NTHREADS + threadIdx.x;   // pixel id
    int w = idx & (WW - 1);
    int h = (idx >> 9) & (HH - 1);
    int b = idx >> 18;

    const size_t bstride = (size_t)CC * PLANE;
    const float* ab = atts + (size_t)b * bstride;
    const float* db = dets + (size_t)b * bstride;
    const float* cb = con  + (size_t)b * bstride;

    // con_target channel bitmask (binary targets)
    unsigned msk = 0;
    {
        const float* ct = cb + h * WW + w;
#pragma unroll
        for (int c = 0; c < 8; c++)
            if (__ldg(ct + c * PLANE) > 0.5f) msk |= (1u << c);
    }

    BranchRes r1 = branch_eval(ab, msk, h, w);   // atts branch
    BranchRes r2 = branch_eval(db, msk, h, w);   // dets branch

    float tg = __ldg(target + (size_t)b * PLANE + h * WW + w);
    bool edge = (msk != 0u) && (msk != 255u);

    float de_p = edge ? (1.0f - r2.vmin) : r2.glo;

    bool T = (tg > 0.5f);
    float b1a = T ? r1.glo : 1.0f - r1.glo;
    float dea = T ? de_p  : 1.0f - de_p;
    float fin = flog2p(b1a, dea);

    float contrib = (0.2f * (r1.bicon + r2.bicon) + 0.8f * (r1.conn + r2.conn))
                        * (1.0f / (float)NEL)
                  + fin * (1.0f / (float)PIX);

    // block reduction: warp shfl -> smem -> one double atomic per block
    __shared__ float wsum[NTHREADS / 32];
#pragma unroll
    for (int o = 16; o > 0; o >>= 1)
        contrib += __shfl_down_sync(0xFFFFFFFFu, contrib, o);
    int lane = threadIdx.x & 31;
    int wid  = threadIdx.x >> 5;
    if (lane == 0) wsum[wid] = contrib;
    __syncthreads();

    if (threadIdx.x == 0) {
        float s = 0.0f;
#pragma unroll
        for (int i = 0; i < NTHREADS / 32; i++) s += wsum[i];
        atomicAdd(&g_acc, (double)s);
        __threadfence();
        unsigned old = atomicInc(&g_count, NBLK - 1u);  // wraps to 0 on last
        if (old == NBLK - 1u) {
            unsigned long long raw =
                atomicExch((unsigned long long*)&g_acc, 0ULL);
            out[0] = -(float)__longlong_as_double(raw);
        }
    }
}

extern "C" void kernel_launch(void* const* d_in, const int* in_sizes, int n_in,
                              void* d_out, int out_size) {
    const float* atts   = (const float*)d_in[0];
    const float* dets   = (const float*)d_in[1];
    const float* target = (const float*)d_in[2];
    const float* con    = (const float*)d_in[3];
    float* out = (float*)d_out;

    bicon_loss_kernel<<<NBLK, NTHREADS>>>(atts, dets, target, con, out);
}

// round 4
// speedup vs baseline: 2.1574x; 1.1589x over previous
#include <cuda_runtime.h>
#include <cstdint>

#define BB 8
#define CC 8
#define HH 512
#define WW 512
#define PLANE (HH*WW)                 // 262144
#define PIX   (BB*HH*WW)              // 2097152
#define NEL   (BB*CC*HH*WW)           // 16777216

#define NTHREADS 128                  // one image row per block (128 strips of 4)
#define NBLK (HH*BB)                  // 4096 blocks

__device__ double       g_acc;        // zero-init; reset by last block each run
__device__ unsigned int g_count;      // wraps to 0 via atomicInc

// sigmoid via single-MUFU tanh.approx: sigma(x) = 0.5 + 0.5*tanh(x/2)
__device__ __forceinline__ float sigt(float x) {
    float t;
    asm("tanh.approx.f32 %0, %1;" : "=f"(t) : "f"(0.5f * x));
    return fmaf(0.5f, t, 0.5f);
}
__device__ __forceinline__ float4 ld4(const float* __restrict__ p) {
    return *reinterpret_cast<const float4*>(p);
}
__device__ __forceinline__ void sig4s(float4 x, float d[4]) {
    d[0] = sigt(x.x); d[1] = sigt(x.y); d[2] = sigt(x.z); d[3] = sigt(x.w);
}
__device__ __forceinline__ float clog(float x) {
    return fmaxf(__logf(x), -100.0f);   // matches jnp.clip(log(x), -100)
}
__device__ __forceinline__ float flog2p(float a, float b) {
    float p = a * b;
    if (p >= 1e-30f) return __logf(p);
    return clog(a) + clog(b);
}

// One vote slot k: center channel k sigmoids S[4], neighbor sigmoids nbv[4].
// Accumulates glo, min, product-of-A (bicon), product-of-B (conn) per pixel;
// exact zeros (padded borders) are diverted to the -100 counter npen.
#define SLOT(k, S, NB0, NB1, NB2, NB3) do {                                   \
    const float nbv[4] = {NB0, NB1, NB2, NB3};                                \
    float* pa = ((k) < 4) ? pA0 : pA1;                                        \
    float* pb = ((k) < 4) ? pB0 : pB1;                                        \
    _Pragma("unroll")                                                         \
    for (int p = 0; p < 4; p++) {                                             \
        float sv = (S)[p];                                                    \
        float v  = sv * nbv[p];                                               \
        glo[p] += v;                                                          \
        mn[p]   = fminf(mn[p], v);                                            \
        bool  t = (m[p] >> (k)) & 1u;                                         \
        float A = t ? v : 1.0f - v;                                           \
        bool  z = (A == 0.0f);                                                \
        npen[p] += z ? 1 : 0;                                                 \
        A = z ? 1.0f : A;                                                     \
        pa[p] *= A;                                                           \
        float Bv = t ? sv : 1.0f - sv;                                        \
        pb[p] *= Bv;                                                          \
    } } while (0)

__device__ __forceinline__ void branch_acc(
    const float* __restrict__ xb, int h, int w0,
    bool hm, bool hp, bool wlo, bool whi,
    const unsigned m[4], float glo[4], float mn[4], float bcon[4])
{
    const float* pc = xb + h * WW + w0;

    // center sigmoids, 8 channels x 4 pixels
    float sc[8][4];
#pragma unroll
    for (int c = 0; c < 8; c++) sig4s(ld4(pc + c * PLANE), sc[c]);

    // neighbor rows (zero where out of bounds -> padded shift = 0)
    float n7m[4] = {0,0,0,0}, n6m[4] = {0,0,0,0}, n5m[4] = {0,0,0,0};
    float n2p[4] = {0,0,0,0}, n1p[4] = {0,0,0,0}, n0p[4] = {0,0,0,0};
    float e7 = 0.f, e5 = 0.f, e2 = 0.f, e0 = 0.f;

    if (hm) {   // uniform per block
        const float* pm = xb + (h - 1) * WW + w0;
        sig4s(ld4(pm + 7 * PLANE), n7m);
        sig4s(ld4(pm + 6 * PLANE), n6m);
        sig4s(ld4(pm + 5 * PLANE), n5m);
        if (!wlo) e7 = sigt(__ldg(pm + 7 * PLANE - 1));
        if (!whi) e5 = sigt(__ldg(pm + 5 * PLANE + 4));
    }
    if (hp) {
        const float* pp = xb + (h + 1) * WW + w0;
        sig4s(ld4(pp + 2 * PLANE), n2p);
        sig4s(ld4(pp + 1 * PLANE), n1p);
        sig4s(ld4(pp + 0 * PLANE), n0p);
        if (!wlo) e2 = sigt(__ldg(pp + 2 * PLANE - 1));
        if (!whi) e0 = sigt(__ldg(pp + 0 * PLANE + 4));
    }
    float e4 = wlo ? 0.f : sigt(__ldg(pc + 4 * PLANE - 1));
    float e3 = whi ? 0.f : sigt(__ldg(pc + 3 * PLANE + 4));

    float pA0[4] = {1,1,1,1}, pA1[4] = {1,1,1,1};
    float pB0[4] = {1,1,1,1}, pB1[4] = {1,1,1,1};
    int   npen[4] = {0,0,0,0};

    // vote slots: v[k] = s_k(h,w) * sigma_{pair}(h+dh, w+dw)
    SLOT(0, sc[0], e7,      n7m[0], n7m[1], n7m[2]);   // a7: c0 * s7(h-1,w-1)
    SLOT(1, sc[1], n6m[0], n6m[1], n6m[2], n6m[3]);    // a3: c1 * s6(h-1,w)
    SLOT(2, sc[2], n5m[1], n5m[2], n5m[3], e5);        // a5: c2 * s5(h-1,w+1)
    SLOT(3, sc[3], e4,      sc[4][0], sc[4][1], sc[4][2]); // a1: c3 * s4(h,w-1)
    SLOT(4, sc[4], sc[3][1], sc[3][2], sc[3][3], e3);  // a2: c4 * s3(h,w+1)
    SLOT(5, sc[5], e2,      n2p[0], n2p[1], n2p[2]);   // a6: c5 * s2(h+1,w-1)
    SLOT(6, sc[6], n1p[0], n1p[1], n1p[2], n1p[3]);    // a4: c6 * s1(h+1,w)
    SLOT(7, sc[7], n0p[1], n0p[2], n0p[3], e0);        // a8: c7 * s0(h+1,w+1)

#pragma unroll
    for (int p = 0; p < 4; p++) {
        float bic = __logf(pA0[p]) + __logf(pA1[p]) - 100.0f * (float)npen[p];
        float con = __logf(pB0[p]) + __logf(pB1[p]);
        bcon[p] += 0.2f * bic + 0.8f * con;
    }
}

__global__ void __launch_bounds__(NTHREADS)
bicon_loss_kernel(const float* __restrict__ atts,
                  const float* __restrict__ dets,
                  const float* __restrict__ target,
                  const float* __restrict__ con,
                  float* __restrict__ out)
{
    const int h  = blockIdx.x & (HH - 1);   // uniform per block
    const int b  = blockIdx.x >> 9;
    const int w0 = threadIdx.x << 2;        // 4-pixel strip
    const bool hm = (h > 0), hp = (h < HH - 1);
    const bool wlo = (w0 == 0), whi = (w0 == WW - 4);

    const size_t bst = (size_t)CC * PLANE;
    const float* ab = atts + (size_t)b * bst;
    const float* db = dets + (size_t)b * bst;

    // con_target bitmasks, one per pixel (binary targets)
    unsigned m[4] = {0, 0, 0, 0};
    {
        const float* cb = con + (size_t)b * bst + h * WW + w0;
#pragma unroll
        for (int c = 0; c < 8; c++) {
            float4 t4 = ld4(cb + c * PLANE);
            m[0] |= (t4.x > 0.5f) << c;
            m[1] |= (t4.y > 0.5f) << c;
            m[2] |= (t4.z > 0.5f) << c;
            m[3] |= (t4.w > 0.5f) << c;
        }
    }
    float4 tg4 = ld4(target + (size_t)b * PLANE + h * WW + w0);
    const float tg[4] = {tg4.x, tg4.y, tg4.z, tg4.w};

    float g1[4] = {0,0,0,0}, g2[4] = {0,0,0,0};
    float mn1[4] = {1e30f,1e30f,1e30f,1e30f}, mn2[4] = {1e30f,1e30f,1e30f,1e30f};
    float bcon[4] = {0,0,0,0};

    branch_acc(ab, h, w0, hm, hp, wlo, whi, m, g1, mn1, bcon);  // atts
    branch_acc(db, h, w0, hm, hp, wlo, whi, m, g2, mn2, bcon);  // dets

    float contrib = 0.0f;
#pragma unroll
    for (int p = 0; p < 4; p++) {
        float gm1 = g1[p] * 0.125f;
        float gm2 = g2[p] * 0.125f;
        bool edge = (m[p] != 0u) && (m[p] != 255u);
        float de  = edge ? (1.0f - mn2[p]) : gm2;
        bool  T   = (tg[p] > 0.5f);
        float x1  = T ? gm1 : 1.0f - gm1;
        float x2  = T ? de  : 1.0f - de;
        contrib += flog2p(x1, x2) * (1.0f / (float)PIX);
    }
    contrib += (bcon[0] + bcon[1] + bcon[2] + bcon[3]) * (1.0f / (float)NEL);

    // block reduction: warp shfl -> smem -> one double atomic per block
    __shared__ float wsum[NTHREADS / 32];
#pragma unroll
    for (int o = 16; o > 0; o >>= 1)
        contrib += __shfl_down_sync(0xFFFFFFFFu, contrib, o);
    int lane = threadIdx.x & 31;
    int wid  = threadIdx.x >> 5;
    if (lane == 0) wsum[wid] = contrib;
    __syncthreads();

    if (threadIdx.x == 0) {
        float s = 0.0f;
#pragma unroll
        for (int i = 0; i < NTHREADS / 32; i++) s += wsum[i];
        atomicAdd(&g_acc, (double)s);
        __threadfence();
        unsigned old = atomicInc(&g_count, NBLK - 1u);  // wraps to 0 on last
        if (old == NBLK - 1u) {
            unsigned long long raw =
                atomicExch((unsigned long long*)&g_acc, 0ULL);
            out[0] = -(float)__longlong_as_double(raw);
        }
    }
}

extern "C" void kernel_launch(void* const* d_in, const int* in_sizes, int n_in,
                              void* d_out, int out_size) {
    const float* atts   = (const float*)d_in[0];
    const float* dets   = (const float*)d_in[1];
    const float* target = (const float*)d_in[2];
    const float* con    = (const float*)d_in[3];
    float* out = (float*)d_out;

    bicon_loss_kernel<<<NBLK, NTHREADS>>>(atts, dets, target, con, out);
}

// round 5
// speedup vs baseline: 2.3520x; 1.0902x over previous
#include <cuda_runtime.h>
#include <cstdint>

#define BB 8
#define CC 8
#define HH 512
#define WW 512
#define PLANE (HH*WW)                 // 262144
#define PIX   (BB*HH*WW)              // 2097152
#define NEL   (BB*CC*HH*WW)           // 16777216

#define TPB   64                      // threads per block (2 warps)
#define RPT   8                       // rows per thread
#define CPB   (TPB*4)                 // 256 cols per block
#define NBX   (WW/CPB)                // 2
#define NBY   (HH/RPT)                // 64
#define NBLK  (NBX*NBY*BB)            // 1024

__device__ double       g_acc;        // zero-init; reset by last block each run
__device__ unsigned int g_count;      // wraps to 0 via atomicInc

// sigmoid via single-MUFU tanh.approx: sigma(x) = 0.5 + 0.5*tanh(x/2)
__device__ __forceinline__ float sigt(float x) {
    float t;
    asm("tanh.approx.f32 %0, %1;" : "=f"(t) : "f"(0.5f * x));
    return fmaf(0.5f, t, 0.5f);
}
__device__ __forceinline__ float4 ld4(const float* __restrict__ p) {
    return *reinterpret_cast<const float4*>(p);
}
__device__ __forceinline__ float clog(float x) {
    return fmaxf(__logf(x), -100.0f);   // matches jnp.clip(log(x), -100)
}

__device__ __forceinline__ void sigrow(const float* __restrict__ base, float S[8][4]) {
#pragma unroll
    for (int c = 0; c < 8; c++) {
        float4 x = ld4(base + c * PLANE);
        S[c][0] = sigt(x.x); S[c][1] = sigt(x.y);
        S[c][2] = sigt(x.z); S[c][3] = sigt(x.w);
    }
}

// value at column w0-1 of the same row/channel: left lane's a[3]; lane-0 fixup LDG
__device__ __forceinline__ float getL(const float a[4], const float* __restrict__ g,
                                      bool ok, int lane) {
    float v = __shfl_up_sync(0xffffffffu, a[3], 1);
    if (lane == 0) v = ok ? sigt(__ldg(g)) : 0.0f;
    return v;
}
// value at column w0+4: right lane's a[0]; lane-31 fixup LDG
__device__ __forceinline__ float getR(const float a[4], const float* __restrict__ g,
                                      bool ok, int lane) {
    float v = __shfl_down_sync(0xffffffffu, a[0], 1);
    if (lane == 31) v = ok ? sigt(__ldg(g)) : 0.0f;
    return v;
}

// con_target bitmasks (4 px x 8 bits) + target bits packed into one u64
__device__ __forceinline__ unsigned long long build_mask(
        const float* __restrict__ cb, const float* __restrict__ tb) {
    unsigned m0 = 0, m1 = 0, m2 = 0, m3 = 0;
#pragma unroll
    for (int c = 0; c < 8; c++) {
        float4 t = ld4(cb + c * PLANE);
        m0 |= ((unsigned)(t.x > 0.5f)) << c;
        m1 |= ((unsigned)(t.y > 0.5f)) << c;
        m2 |= ((unsigned)(t.z > 0.5f)) << c;
        m3 |= ((unsigned)(t.w > 0.5f)) << c;
    }
    float4 tg = ld4(tb);
    unsigned t4 = (unsigned)(tg.x > 0.5f) | ((unsigned)(tg.y > 0.5f) << 1)
                | ((unsigned)(tg.z > 0.5f) << 2) | ((unsigned)(tg.w > 0.5f) << 3);
    return (unsigned long long)(m0 | (m1 << 8) | (m2 << 16) | (m3 << 24))
         | ((unsigned long long)t4 << 32);
}

// votes + loss terms for one row of a 4-pixel strip.
// Shm: ch5,6,7 sigmoids at row r-1; C: all 8 ch at row r; Sn: ch0,1,2 at row r+1.
__device__ __forceinline__ float row_votes(
    const float Shm[3][4], const float C[8][4], const float Sn[3][4],
    const float* __restrict__ xb, int r, int w0,
    bool wlo, bool whi, int lane, bool hmok, bool hpok,
    unsigned long long mp, int pass)
{
    const float* rm = xb + (r - 1) * WW + w0;
    const float* rc = xb + r * WW + w0;
    const float* rp = xb + (r + 1) * WW + w0;

    float L7 = getL(Shm[2], rm + 7 * PLANE - 1, hmok && !wlo, lane);
    float R5 = getR(Shm[0], rm + 5 * PLANE + 4, hmok && !whi, lane);
    float L4 = getL(C[4],   rc + 4 * PLANE - 1, !wlo,         lane);
    float R3 = getR(C[3],   rc + 3 * PLANE + 4, !whi,         lane);
    float L2 = getL(Sn[2],  rp + 2 * PLANE - 1, hpok && !wlo, lane);
    float R0 = getR(Sn[0],  rp + 0 * PLANE + 4, hpok && !whi, lane);

    float accb = 0.0f, accp = 0.0f;
#pragma unroll
    for (int p = 0; p < 4; p++) {
        float nb[8];
        nb[0] = (p == 0) ? L7 : Shm[2][p == 0 ? 0 : p - 1];   // c7(r-1, w-1)
        nb[1] = Shm[1][p];                                    // c6(r-1, w)
        nb[2] = (p == 3) ? R5 : Shm[0][p == 3 ? 3 : p + 1];   // c5(r-1, w+1)
        nb[3] = (p == 0) ? L4 : C[4][p == 0 ? 0 : p - 1];     // c4(r,   w-1)
        nb[4] = (p == 3) ? R3 : C[3][p == 3 ? 3 : p + 1];     // c3(r,   w+1)
        nb[5] = (p == 0) ? L2 : Sn[2][p == 0 ? 0 : p - 1];    // c2(r+1, w-1)
        nb[6] = Sn[1][p];                                     // c1(r+1, w)
        nb[7] = (p == 3) ? R0 : Sn[0][p == 3 ? 3 : p + 1];    // c0(r+1, w+1)

        unsigned m = (unsigned)(mp >> (8 * p)) & 0xFFu;
        bool T = (mp >> (32 + p)) & 1ull;

        float pA0 = 1.f, pA1 = 1.f, pB0 = 1.f, pB1 = 1.f;
        float glo = 0.f, mn = 1e30f;
        int npen = 0;
#pragma unroll
        for (int k = 0; k < 8; k++) {
            float s = C[k][p];
            float v = s * nb[k];
            glo += v;
            mn = fminf(mn, v);
            bool t = (m >> k) & 1u;
            float A = t ? v : 1.0f - v;
            if (A == 0.0f) { npen++; A = 1.0f; }   // padded border: exact -100 later
            float Bv = t ? s : 1.0f - s;
            if (k < 4) { pA0 *= A; pB0 *= Bv; }
            else       { pA1 *= A; pB1 *= Bv; }
        }
        float bic = __logf(pA0) + __logf(pA1) - 100.0f * (float)npen;
        float co  = __logf(pB0) + __logf(pB1);
        accb += 0.2f * bic + 0.8f * co;

        float g = glo * 0.125f;
        float x;
        if (pass == 0) {
            x = T ? g : 1.0f - g;                        // bce_loss1
        } else {
            bool edge = (m != 0u) && (m != 255u);
            float de  = edge ? (1.0f - mn) : g;          // decouple map
            x = T ? de : 1.0f - de;
        }
        accp += clog(x);
    }
    return accb * (1.0f / (float)NEL) + accp * (1.0f / (float)PIX);
}

__global__ void __launch_bounds__(TPB, 7)
bicon_loss_kernel(const float* __restrict__ atts,
                  const float* __restrict__ dets,
                  const float* __restrict__ target,
                  const float* __restrict__ con,
                  float* __restrict__ out)
{
    __shared__ unsigned long long mk[RPT * TPB];   // 4 KB mask cache
    __shared__ float wsum[TPB / 32];

    const int tid  = threadIdx.x;
    const int lane = tid & 31;
    const int bid  = blockIdx.x;
    const int cpart = bid & (NBX - 1);
    const int band  = (bid / NBX) & (NBY - 1);
    const int b     = bid / (NBX * NBY);
    const int w0 = cpart * CPB + tid * 4;
    const int r0 = band * RPT;
    const bool wlo = (w0 == 0), whi = (w0 + 4 == WW);

    const size_t bst = (size_t)CC * PLANE;
    const float* cb0 = con + (size_t)b * bst;
    const float* tb0 = target + (size_t)b * PLANE;

    float contrib = 0.0f;

#pragma unroll
    for (int pass = 0; pass < 2; pass++) {
        const float* xb = (pass ? dets : atts) + (size_t)b * bst;

        // prologue: row r0-1 channels 5,6,7; row r0 full
        float Shm[3][4];
        if (r0 > 0) {
            const float* pm = xb + (r0 - 1) * WW + w0;
#pragma unroll
            for (int j = 0; j < 3; j++) {
                float4 x = ld4(pm + (5 + j) * PLANE);
                Shm[j][0] = sigt(x.x); Shm[j][1] = sigt(x.y);
                Shm[j][2] = sigt(x.z); Shm[j][3] = sigt(x.w);
            }
        } else {
#pragma unroll
            for (int j = 0; j < 3; j++)
#pragma unroll
                for (int p = 0; p < 4; p++) Shm[j][p] = 0.0f;
        }
        float C[8][4];
        sigrow(xb + r0 * WW + w0, C);

#pragma unroll 1
        for (int i = 0; i < RPT - 1; i++) {
            const int r = r0 + i;
            unsigned long long mp;
            if (pass == 0) {
                mp = build_mask(cb0 + r * WW + w0, tb0 + r * WW + w0);
                mk[i * TPB + tid] = mp;
            } else {
                mp = mk[i * TPB + tid];
            }
            float N[8][4];
            sigrow(xb + (r + 1) * WW + w0, N);   // prefetch+convert next row

            contrib += row_votes(Shm, C, N, xb, r, w0, wlo, whi, lane,
                                 r > 0, true, mp, pass);
            // roll
#pragma unroll
            for (int j = 0; j < 3; j++)
#pragma unroll
                for (int p = 0; p < 4; p++) Shm[j][p] = C[5 + j][p];
#pragma unroll
            for (int c = 0; c < 8; c++)
#pragma unroll
                for (int p = 0; p < 4; p++) C[c][p] = N[c][p];
        }
        {   // last row of band: next row needs only channels 0,1,2
            const int r = r0 + RPT - 1;
            unsigned long long mp;
            if (pass == 0) {
                mp = build_mask(cb0 + r * WW + w0, tb0 + r * WW + w0);
                mk[(RPT - 1) * TPB + tid] = mp;
            } else {
                mp = mk[(RPT - 1) * TPB + tid];
            }
            const bool hpok = (r + 1 < HH);
            float Sn[3][4];
            if (hpok) {
                const float* pp = xb + (r + 1) * WW + w0;
#pragma unroll
                for (int c = 0; c < 3; c++) {
                    float4 x = ld4(pp + c * PLANE);
                    Sn[c][0] = sigt(x.x); Sn[c][1] = sigt(x.y);
                    Sn[c][2] = sigt(x.z); Sn[c][3] = sigt(x.w);
                }
            } else {
#pragma unroll
                for (int c = 0; c < 3; c++)
#pragma unroll
                    for (int p = 0; p < 4; p++) Sn[c][p] = 0.0f;
            }
            contrib += row_votes(Shm, C, Sn, xb, r, w0, wlo, whi, lane,
                                 true, hpok, mp, pass);
        }
    }

    // block reduction: warp shfl -> smem -> one double atomic per block
#pragma unroll
    for (int o = 16; o > 0; o >>= 1)
        contrib += __shfl_down_sync(0xFFFFFFFFu, contrib, o);
    if (lane == 0) wsum[tid >> 5] = contrib;
    __syncthreads();

    if (tid == 0) {
        float s = 0.0f;
#pragma unroll
        for (int i = 0; i < TPB / 32; i++) s += wsum[i];
        atomicAdd(&g_acc, (double)s);
        __threadfence();
        unsigned old = atomicInc(&g_count, NBLK - 1u);   // wraps to 0 on last
        if (old == NBLK - 1u) {
            unsigned long long raw =
                atomicExch((unsigned long long*)&g_acc, 0ULL);
            out[0] = -(float)__longlong_as_double(raw);
        }
    }
}

extern "C" void kernel_launch(void* const* d_in, const int* in_sizes, int n_in,
                              void* d_out, int out_size) {
    const float* atts   = (const float*)d_in[0];
    const float* dets   = (const float*)d_in[1];
    const float* target = (const float*)d_in[2];
    const float* con    = (const float*)d_in[3];
    float* out = (float*)d_out;

    bicon_loss_kernel<<<NBLK, TPB>>>(atts, dets, target, con, out);
}